// round 15
// baseline (speedup 1.0000x reference)
#include <cuda_runtime.h>
#include <cuda_fp16.h>
#include <math.h>
#include <stdint.h>

#define NN (64*4096)
#define NE (64*16384)
#define NS (64*1024)
#define NN2 (NN/2)
#define NE2 (NE/2)
#define NS2 (NS/2)
#define IN_F 26

typedef unsigned long long ull;

__device__ __align__(16) float g_agg[(size_t)NN * 64];
__device__ __align__(16) float g_conv[(size_t)NN * 64];
__device__ __align__(16) __half2 g_Ph[(size_t)NN * 64];   // [node][Psrc 32 | Pdst 32] half2
__device__ unsigned g_flagbits[NN / 32];                  // idempotent across replays
__device__ int4  g_sde[NE];
__device__ int   g_nlist[NN];
__device__ int   g_cnt[8];
__device__ __align__(16) __half g_Wlh[512 * 512];
__device__ __align__(16) __half g_Weh[64 * 128];
__device__ __align__(16) __half g_Wd1h[256 * 64];
__device__ __align__(16) float  g_bc[2 * 512];

__device__ __forceinline__ ull pk(float lo, float hi) {
    ull r; asm("mov.b64 %0, {%1, %2};" : "=l"(r) : "f"(lo), "f"(hi)); return r;
}
__device__ __forceinline__ ull pk2(float v) { return pk(v, v); }
__device__ __forceinline__ float2 upk(ull v) {
    float2 r; asm("mov.b64 {%0, %1}, %2;" : "=f"(r.x), "=f"(r.y) : "l"(v)); return r;
}
__device__ __forceinline__ ull fma2(ull a, ull b, ull c) {
    ull d; asm("fma.rn.f32x2 %0, %1, %2, %3;" : "=l"(d) : "l"(a), "l"(b), "l"(c)); return d;
}
__device__ __forceinline__ float fsig(float x)  { return __fdividef(1.f, 1.f + __expf(-x)); }
__device__ __forceinline__ float ftanh(float x) { return 1.f - __fdividef(2.f, 1.f + __expf(2.f * x)); }

__device__ __forceinline__ float tf32v(float f) {
    uint32_t r; asm("cvt.rna.tf32.f32 %0, %1;" : "=r"(r) : "f"(f));
    return __uint_as_float(r);
}
__device__ __forceinline__ void mma8(float* d, const uint32_t* a, uint32_t b0, uint32_t b1) {
    asm volatile(
        "mma.sync.aligned.m16n8k8.row.col.f32.tf32.tf32.f32 "
        "{%0,%1,%2,%3}, {%4,%5,%6,%7}, {%8,%9}, {%0,%1,%2,%3};"
        : "+f"(d[0]), "+f"(d[1]), "+f"(d[2]), "+f"(d[3])
        : "r"(a[0]), "r"(a[1]), "r"(a[2]), "r"(a[3]), "r"(b0), "r"(b1));
}
__device__ __forceinline__ uint32_t ldb(const float* p) { return __float_as_uint(*p); }
__device__ __forceinline__ uint32_t ldh(const __half* p) {
    return __float_as_uint(__half2float(*p));
}
__device__ __forceinline__ uint32_t h2u(__half2 h) {
    uint32_t u; *(__half2*)&u = h; return u;
}
__device__ __forceinline__ void cp16(uint32_t dst, const void* src) {
    asm volatile("cp.async.cg.shared.global [%0], [%1], 16;" :: "r"(dst), "l"(src));
}
#define CP_COMMIT() asm volatile("cp.async.commit_group;")
#define CP_WAIT(n)  asm volatile("cp.async.wait_group " #n ";")
__device__ __forceinline__ void redv2(float* p, float a, float b) {
    asm volatile("red.global.add.v2.f32 [%0], {%1, %2};" :: "l"(p), "f"(a), "f"(b) : "memory");
}

// ---------------- prep: fp16 weight conversion ----------------
__global__ __launch_bounds__(256) void prep_kernel(
    const float* __restrict__ Wih0, const float* __restrict__ Whh0,
    const float* __restrict__ Wih1, const float* __restrict__ Whh1,
    const float* __restrict__ We,   const float* __restrict__ Wd1,
    const float* __restrict__ bih0, const float* __restrict__ bhh0,
    const float* __restrict__ bih1, const float* __restrict__ bhh1)
{
    int i = blockIdx.x * 256 + threadIdx.x;
    if (i < 262144) {
        int cell = i >> 17, r = (i >> 9) & 255, n = i & 511;
        const float* W = (r < 128) ? (cell ? Wih1 : Wih0) : (cell ? Whh1 : Whh0);
        g_Wlh[i] = __float2half(W[(r & 127) * 512 + n]);
    } else if (i < 270336) {
        int j = i - 262144; g_Weh[j] = __float2half(We[j]);
    } else if (i < 286720) {
        int j = i - 270336; g_Wd1h[j] = __float2half(Wd1[j]);
    } else if (i < 287744) {
        int j = i - 286720; int cell = j >> 9; int n = j & 511;
        g_bc[j] = cell ? (bih1[n] + bhh1[n]) : (bih0[n] + bhh0[n]);
    }
}

// ---------------- preall: P for ALL nodes (off the critical chain) ----------------
__global__ __launch_bounds__(256) void preall_kernel(
    const float* __restrict__ x, const float* __restrict__ Wm,
    const float* __restrict__ bm)
{
    __shared__ float Ws[52 * 64];
    __shared__ float bs[64];
    for (int i = threadIdx.x; i < 52 * 64; i += 256) Ws[i] = Wm[i];
    if (threadIdx.x < 64) bs[threadIdx.x] = bm[threadIdx.x];
    __syncthreads();

    int gid  = blockIdx.x * 256 + threadIdx.x;   // over 2*NN
    int n    = gid >> 1;
    int half = gid & 1;

    ull acc[32];
#pragma unroll
    for (int j = 0; j < 32; j++)
        acc[j] = half ? 0ull : pk(bs[2 * j], bs[2 * j + 1]);

    const float2* xr = (const float2*)(x + (size_t)n * IN_F);
    const int rbase = half * IN_F;
#pragma unroll
    for (int kk = 0; kk < 13; kk++) {
        float2 xv = xr[kk];
#pragma unroll
        for (int hh = 0; hh < 2; hh++) {
            ull v = pk2(hh ? xv.y : xv.x);
            const ulonglong2* wr = (const ulonglong2*)&Ws[(rbase + 2 * kk + hh) * 64];
#pragma unroll
            for (int j = 0; j < 16; j++) {
                ulonglong2 w = wr[j];
                acc[2 * j]     = fma2(v, w.x, acc[2 * j]);
                acc[2 * j + 1] = fma2(v, w.y, acc[2 * j + 1]);
            }
        }
    }
    uint4* dst = (uint4*)(g_Ph + (size_t)n * 64 + half * 32);
#pragma unroll
    for (int j = 0; j < 8; j++) {
        float2 a = upk(acc[4 * j]),     b = upk(acc[4 * j + 1]);
        float2 c = upk(acc[4 * j + 2]), d = upk(acc[4 * j + 3]);
        uint4 v;
        v.x = h2u(__floats2half2_rn(a.x, a.y));
        v.y = h2u(__floats2half2_rn(b.x, b.y));
        v.z = h2u(__floats2half2_rn(c.x, c.y));
        v.w = h2u(__floats2half2_rn(d.x, d.y));
        dst[j] = v;
    }
}

// ---------------- flag + zero agg rows + zero counters ----------------
__global__ __launch_bounds__(256) void flag_zero_kernel(const int* __restrict__ si, int h) {
    if (blockIdx.x == 0 && threadIdx.x < 4) g_cnt[h * 4 + threadIdx.x] = 0;
    int gw = blockIdx.x * 8 + (threadIdx.x >> 5);
    int l  = threadIdx.x & 31;
    int n  = si[h * NS2 + gw];
    if (l == 0) atomicOr(&g_flagbits[n >> 5], 1u << (n & 31));
    ((float2*)(g_agg + (size_t)n * 64))[l] = make_float2(0.f, 0.f);
}

__global__ __launch_bounds__(256) void compact_edges_kernel(const int* __restrict__ ei, int h) {
    int e = h * NE2 + blockIdx.x * 256 + threadIdx.x;
    int d = ei[NE + e];
    bool act = (g_flagbits[d >> 5] >> (d & 31)) & 1u;
    unsigned m = __ballot_sync(0xffffffffu, act);
    if (m) {
        int lane = threadIdx.x & 31;
        int leader = __ffs(m) - 1;
        int pos = 0;
        if (lane == leader) pos = atomicAdd(&g_cnt[h * 4], __popc(m));
        pos = __shfl_sync(0xffffffffu, pos, leader);
        pos += __popc(m & ((1u << lane) - 1));
        if (act) g_sde[h * NE2 + pos] = make_int4(ei[e], d, e, 0);
    }
}

__global__ __launch_bounds__(256) void compact_nodes_kernel(int h) {
    int n = h * NN2 + blockIdx.x * 256 + threadIdx.x;
    int lane = threadIdx.x & 31;
    bool a = (g_flagbits[n >> 5] >> (n & 31)) & 1u;
    unsigned m = __ballot_sync(0xffffffffu, a);
    if (m) {
        int leader = __ffs(m) - 1;
        int pos = 0;
        if (lane == leader) pos = atomicAdd(&g_cnt[h * 4 + 1], __popc(m));
        pos = __shfl_sync(0xffffffffu, pos, leader);
        pos += __popc(m & ((1u << lane) - 1));
        if (a) g_nlist[h * NN2 + pos] = n;
    }
}

// ---------------- edges: fp16 P gathers ----------------
__global__ __launch_bounds__(256) void edge_kernel(const float* __restrict__ ea,
                                                   const float* __restrict__ Wm, int h)
{
    __shared__ float Ws[15 * 64];
    for (int i = threadIdx.x; i < 15 * 64; i += 256) Ws[i] = Wm[52 * 64 + i];
    __syncthreads();

    const int l  = threadIdx.x & 31;
    const int gw = blockIdx.x * 8 + (threadIdx.x >> 5);
    const int W  = gridDim.x * 8;
    const int ec = g_cnt[h * 4];

    for (int i = gw; i < ec; i += W) {
        int4 sde = g_sde[h * NE2 + i];
        float2 fs = __half22float2(g_Ph[(size_t)sde.x * 64 + l]);
        float2 fd = __half22float2(g_Ph[(size_t)sde.y * 64 + 32 + l]);
        ull acc = pk(fs.x + fd.x, fs.y + fd.y);
        const float* er = ea + (size_t)sde.z * 15;
#pragma unroll
        for (int k = 0; k < 15; k++) {
            ull w = *(const ull*)&Ws[k * 64 + 2 * l];
            acc = fma2(pk2(er[k]), w, acc);
        }
        float2 a = upk(acc);
        redv2(g_agg + (size_t)sde.y * 64 + 2 * l, fmaxf(a.x, 0.f), fmaxf(a.y, 0.f));
    }
}

__global__ __launch_bounds__(256) void node_kernel(
    const float* __restrict__ x, const float* __restrict__ Wn,
    const float* __restrict__ bn, int h)
{
    __shared__ float Ws[90 * 64];
    __shared__ float bs[64];
    for (int i = threadIdx.x; i < 90 * 64; i += 256) Ws[i] = Wn[i];
    if (threadIdx.x < 64) bs[threadIdx.x] = bn[threadIdx.x];
    __syncthreads();

    int i = blockIdx.x * 256 + threadIdx.x;
    if (i >= g_cnt[h * 4 + 1]) return;
    int n = g_nlist[h * NN2 + i];

    ull acc[32];
#pragma unroll
    for (int j = 0; j < 32; j++) acc[j] = pk(bs[2 * j], bs[2 * j + 1]);

    const float2* xr = (const float2*)(x + (size_t)n * IN_F);
#pragma unroll
    for (int kk = 0; kk < 13; kk++) {
        float2 xv = xr[kk];
#pragma unroll
        for (int hh = 0; hh < 2; hh++) {
            ull v = pk2(hh ? xv.y : xv.x);
            const ulonglong2* wr = (const ulonglong2*)&Ws[(2 * kk + hh) * 64];
#pragma unroll
            for (int j = 0; j < 16; j++) {
                ulonglong2 w = wr[j];
                acc[2 * j]     = fma2(v, w.x, acc[2 * j]);
                acc[2 * j + 1] = fma2(v, w.y, acc[2 * j + 1]);
            }
        }
    }
    const float4* ar = (const float4*)(g_agg + (size_t)n * 64);
#pragma unroll
    for (int kk = 0; kk < 16; kk++) {
        float4 av = ar[kk];
#pragma unroll
        for (int hh = 0; hh < 4; hh++) {
            float vf = hh == 0 ? av.x : hh == 1 ? av.y : hh == 2 ? av.z : av.w;
            ull v = pk2(vf);
            const ulonglong2* wr = (const ulonglong2*)&Ws[(IN_F + 4 * kk + hh) * 64];
#pragma unroll
            for (int j = 0; j < 16; j++) {
                ulonglong2 w = wr[j];
                acc[2 * j]     = fma2(v, w.x, acc[2 * j]);
                acc[2 * j + 1] = fma2(v, w.y, acc[2 * j + 1]);
            }
        }
    }
    float4* dst = (float4*)(g_conv + (size_t)n * 64);
#pragma unroll
    for (int j = 0; j < 16; j++) {
        float2 a = upk(acc[2 * j]), b = upk(acc[2 * j + 1]);
        dst[j] = make_float4(fmaxf(a.x, 0.f), fmaxf(a.y, 0.f),
                             fmaxf(b.x, 0.f), fmaxf(b.y, 0.f));
    }
}

// ---------------- fused sampled pipeline (validated R14 structure, unchanged) ----------------
#define O_NCT 0
#define O_A2  4352
#define O_XT  5632
#define O_HT  14080
#define O_WFL 22528
#define WBUF_H 8320
#define SMEM_BYTES (O_WFL * 4 + 3 * WBUF_H * 2)   // 140032

__global__ __launch_bounds__(512, 1) void sample_kernel(
    const int* __restrict__ sidx_g, const float* __restrict__ gm,
    const float* __restrict__ be, const float* __restrict__ bd1,
    const float* __restrict__ Wd2, const float* __restrict__ bd2,
    float* __restrict__ out, int h)
{
    extern __shared__ float sm[];
    float* nct = sm + O_NCT;
    float* A2  = sm + O_A2;
    float* Xt  = sm + O_XT;
    float* Ht  = sm + O_HT;
    __half* Wsh = (__half*)(sm + O_WFL);
    __shared__ float gmrow[10];
    __shared__ int   sidx[64];

    const int t    = threadIdx.x;
    const int base = h * NS2 + blockIdx.x * 64;
    const uint32_t wsh_u = (uint32_t)__cvta_generic_to_shared(Wsh);

    if (t < 64) sidx[t] = sidx_g[base + t];
    if (t < 10) gmrow[t] = gm[(base >> 10) * 10 + t];

    auto prefetch = [&](int c2) {
        uint32_t db = wsh_u + (uint32_t)((c2 % 3) * WBUF_H) * 2;
        if (c2 < 4) {
            if (t < 256) {
                int idx = t * 8; int kk = idx >> 7, n = idx & 127;
                cp16(db + (uint32_t)(kk * 520 + n) * 2, g_Weh + c2 * 2048 + idx);
            }
        } else if (c2 < 36) {
#pragma unroll
            for (int ii = 0; ii < 2; ii++) {
                int idx = (ii * 512 + t) * 8; int kk = idx >> 9, n = idx & 511;
                cp16(db + (uint32_t)(kk * 520 + n) * 2,
                     g_Wlh + (size_t)(c2 - 4) * 8192 + idx);
            }
        } else if (c2 < 52) {
            if (t < 128) {
                int idx = t * 8; int kk = idx >> 6, n = idx & 63;
                cp16(db + (uint32_t)(kk * 520 + n) * 2,
                     g_Wd1h + (c2 - 36) * 1024 + idx);
            }
        }
        CP_COMMIT();
    };
    prefetch(0);
    prefetch(1);

    __syncthreads();

    float* out_nc = out;
    float* out_h1 = out + (size_t)NS * 64;
    float* out_c1 = out_h1 + (size_t)NS * 128;
    float* out_h2 = out_c1 + (size_t)NS * 128;
    float* out_c2 = out_h2 + (size_t)NS * 128;
    float* out_y  = out_c2 + (size_t)NS * 128;

    for (int idx = t; idx < 64 * 64; idx += 512) {
        int r = idx >> 6, c = idx & 63;
        float v = g_conv[(size_t)sidx[r] * 64 + c];
        nct[r * 68 + c] = tf32v(v);
        out_nc[(size_t)(base + r) * 64 + c] = v;
    }
    for (int idx = t; idx < 64 * 20; idx += 512) {
        int r = idx / 20, kk = idx - r * 20;
        A2[idx] = (kk < 10) ? tf32v(g_conv[(size_t)sidx[r] * 64 + 54 + kk]) : 0.f;
    }
    __syncthreads();

    const int w    = t >> 5;
    const int lane = t & 31;
    const int g8   = lane >> 2;
    const int cc   = lane & 3;
    const int j0   = w * 8;
    const int col0 = j0 + 2 * cc, col1 = col0 + 1;

    float acc[64];
#pragma unroll
    for (int i = 0; i < 64; i++) acc[i] = 0.f;

    // encoder chunks 0..3
#pragma unroll 1
    for (int c = 0; c < 4; c++) {
        CP_WAIT(1);
        __syncthreads();
        prefetch(c + 2);
        const __half* wb = Wsh + (c % 3) * WBUF_H;
#pragma unroll
        for (int ks = 0; ks < 2; ks++) {
            int k0 = c * 16 + ks * 8;
            uint32_t b0 = ldh(&wb[(ks * 8 + cc) * 520 + j0 + g8]);
            uint32_t b1 = ldh(&wb[(ks * 8 + cc + 4) * 520 + j0 + g8]);
#pragma unroll
            for (int mt = 0; mt < 4; mt++) {
                int r0 = mt * 16 + g8;
                uint32_t a[4];
                a[0] = ldb(&nct[r0 * 68 + k0 + cc]);
                a[1] = ldb(&nct[(r0 + 8) * 68 + k0 + cc]);
                a[2] = ldb(&nct[r0 * 68 + k0 + cc + 4]);
                a[3] = ldb(&nct[(r0 + 8) * 68 + k0 + cc + 4]);
                mma8(acc + mt * 4, a, b0, b1);
            }
        }
    }

    // gm-correction mma + encoder epilogue (We rows 54..63 = buffer0 rows 6..15)
    {
        const __half* wb = Wsh;
#pragma unroll
        for (int ks = 0; ks < 2; ks++) {
            int k0 = ks * 8;
            uint32_t b0 = ldh(&wb[(6 + k0 + cc) * 520 + j0 + g8]);
            uint32_t b1 = ldh(&wb[(6 + k0 + cc + 4) * 520 + j0 + g8]);
#pragma unroll
            for (int mt = 0; mt < 4; mt++) {
                int r0 = mt * 16 + g8;
                uint32_t a[4];
                a[0] = ldb(&A2[r0 * 20 + k0 + cc]);
                a[1] = ldb(&A2[(r0 + 8) * 20 + k0 + cc]);
                a[2] = ldb(&A2[r0 * 20 + k0 + cc + 4]);
                a[3] = ldb(&A2[(r0 + 8) * 20 + k0 + cc + 4]);
                mma8(acc + 16 + mt * 4, a, b0, b1);
            }
        }
        float be0 = be[col0], be1 = be[col1];
        float gs0 = 0.f, gs1 = 0.f;
#pragma unroll
        for (int k = 0; k < 10; k++) {
            gs0 = fmaf(gmrow[k], __half2float(wb[(6 + k) * 520 + col0]), gs0);
            gs1 = fmaf(gmrow[k], __half2float(wb[(6 + k) * 520 + col1]), gs1);
        }
#pragma unroll
        for (int mt = 0; mt < 4; mt++) {
#pragma unroll
            for (int pp = 0; pp < 2; pp++) {
                int row = mt * 16 + g8 + pp * 8;
                float hp0 = acc[mt * 4 + pp * 2],      hp1 = acc[mt * 4 + pp * 2 + 1];
                float cr0 = acc[16 + mt * 4 + pp * 2], cr1 = acc[16 + mt * 4 + pp * 2 + 1];
                *(float2*)(Xt + row * 132 + col0) =
                    make_float2(tf32v(fmaxf(hp0 - cr0 + gs0 + be0, 0.f)),
                                tf32v(fmaxf(hp1 - cr1 + gs1 + be1, 0.f)));
                *(float2*)(Ht + row * 132 + col0) =
                    make_float2(tf32v(fmaxf(hp0 + be0, 0.f)),
                                tf32v(fmaxf(hp1 + be1, 0.f)));
            }
        }
#pragma unroll
        for (int i = 0; i < 64; i++) acc[i] = 0.f;
    }
    __syncthreads();

    // LSTM cells: chunks 4..35
#pragma unroll 1
    for (int cell = 0; cell < 2; cell++) {
        const int cbase = 4 + cell * 16;
#pragma unroll 1
        for (int cl = 0; cl < 16; cl++) {
            const int c = cbase + cl;
            CP_WAIT(1);
            __syncthreads();
            prefetch(c + 2);
            const int kl = cl * 16;
            const __half* wb = Wsh + (c % 3) * WBUF_H;
#pragma unroll
            for (int ks = 0; ks < 2; ks++) {
                int kg = kl + ks * 8;
                const float* At_ = (kg < 128) ? (Xt + kg) : (Ht + (kg - 128));
                uint32_t afr[4][4];
#pragma unroll
                for (int mt = 0; mt < 4; mt++) {
                    int r0 = mt * 16 + g8;
                    afr[mt][0] = ldb(&At_[r0 * 132 + cc]);
                    afr[mt][1] = ldb(&At_[(r0 + 8) * 132 + cc]);
                    afr[mt][2] = ldb(&At_[r0 * 132 + cc + 4]);
                    afr[mt][3] = ldb(&At_[(r0 + 8) * 132 + cc + 4]);
                }
#pragma unroll
                for (int q = 0; q < 4; q++) {
                    int ncol = q * 128 + j0 + g8;
                    uint32_t b0 = ldh(&wb[(ks * 8 + cc) * 520 + ncol]);
                    uint32_t b1 = ldh(&wb[(ks * 8 + cc + 4) * 520 + ncol]);
#pragma unroll
                    for (int mt = 0; mt < 4; mt++)
                        mma8(acc + mt * 16 + q * 4, afr[mt], b0, b1);
                }
            }
        }

        __syncthreads();
        {
            const float* bc = g_bc + cell * 512;
            float* oH = cell ? out_h2 : out_h1;
            float* oC = cell ? out_c2 : out_c1;
#pragma unroll
            for (int mt = 0; mt < 4; mt++) {
#pragma unroll
                for (int pp = 0; pp < 2; pp++) {
                    int row = mt * 16 + g8 + pp * 8;
                    int ib  = mt * 16 + pp * 2;
                    float vi0 = acc[ib + 0]  + bc[col0],       vi1 = acc[ib + 1]  + bc[col1];
                    float vf0 = acc[ib + 4]  + bc[128 + col0], vf1 = acc[ib + 5]  + bc[128 + col1];
                    float vg0 = acc[ib + 8]  + bc[256 + col0], vg1 = acc[ib + 9]  + bc[256 + col1];
                    float vo0 = acc[ib + 12] + bc[384 + col0], vo1 = acc[ib + 13] + bc[384 + col1];
                    float cp0 = Ht[row * 132 + col0], cp1 = Ht[row * 132 + col1];
                    float cv0 = fsig(vf0) * cp0 + fsig(vi0) * ftanh(vg0);
                    float cv1 = fsig(vf1) * cp1 + fsig(vi1) * ftanh(vg1);
                    float hv0 = fsig(vo0) * ftanh(cv0);
                    float hv1 = fsig(vo1) * ftanh(cv1);
                    size_t gi = (size_t)(base + row) * 128 + col0;
                    *(float2*)(oH + gi) = make_float2(hv0, hv1);
                    *(float2*)(oC + gi) = make_float2(cv0, cv1);
                    if (cell == 0) {
                        float nx0 = (col0 >= 118) ? gmrow[col0 - 118] : hv0;
                        float nx1 = (col1 >= 118) ? gmrow[col1 - 118] : hv1;
                        *(float2*)(Xt + row * 132 + col0) = make_float2(tf32v(nx0), tf32v(nx1));
                    } else {
                        *(float2*)(Xt + row * 132 + col0) = make_float2(tf32v(hv0), tf32v(hv1));
                        *(float2*)(Ht + row * 132 + col0) = make_float2(tf32v(cv0), tf32v(cv1));
                    }
                }
            }
#pragma unroll
            for (int i = 0; i < 64; i++) acc[i] = 0.f;
        }
        __syncthreads();
    }

    // decoder: chunks 36..51
    {
        const int n0  = (w & 7) * 8;
        const int mt0 = (w >> 3) * 2;
#pragma unroll 1
        for (int dl = 0; dl < 16; dl++) {
            const int c = 36 + dl;
            CP_WAIT(1);
            __syncthreads();
            prefetch(c + 2);
            const __half* wb = Wsh + (c % 3) * WBUF_H;
#pragma unroll
            for (int ks = 0; ks < 2; ks++) {
                int kg = dl * 16 + ks * 8;
                const float* At_ = (kg < 128) ? (Xt + kg) : (Ht + (kg - 128));
                uint32_t b0 = ldh(&wb[(ks * 8 + cc) * 520 + n0 + g8]);
                uint32_t b1 = ldh(&wb[(ks * 8 + cc + 4) * 520 + n0 + g8]);
#pragma unroll
                for (int m = 0; m < 2; m++) {
                    int r0 = (mt0 + m) * 16 + g8;
                    uint32_t a[4];
                    a[0] = ldb(&At_[r0 * 132 + cc]);
                    a[1] = ldb(&At_[(r0 + 8) * 132 + cc]);
                    a[2] = ldb(&At_[r0 * 132 + cc + 4]);
                    a[3] = ldb(&At_[(r0 + 8) * 132 + cc + 4]);
                    mma8(acc + m * 4, a, b0, b1);
                }
            }
        }
        __syncthreads();
        int c0 = n0 + 2 * cc, c1 = c0 + 1;
        float b0 = bd1[c0], b1 = bd1[c1];
#pragma unroll
        for (int m = 0; m < 2; m++) {
#pragma unroll
            for (int pp = 0; pp < 2; pp++) {
                int row = (mt0 + m) * 16 + g8 + pp * 8;
                float v0 = fmaxf(acc[m * 4 + pp * 2]     + b0, 0.f);
                float v1 = fmaxf(acc[m * 4 + pp * 2 + 1] + b1, 0.f);
                *(float2*)(nct + row * 68 + c0) = make_float2(v0, v1);
            }
        }
    }
    __syncthreads();

    if (t < 384) {
        int r = t / 6, c = t - r * 6;
        float accy = bd2[c];
#pragma unroll
        for (int k = 0; k < 64; k++) accy = fmaf(nct[r * 68 + k], Wd2[k * 6 + c], accy);
        out_y[(size_t)(base + r) * 6 + c] = accy;
    }
}

// ----------------------------------------------------------------
extern "C" void kernel_launch(void* const* d_in, const int* in_sizes, int n_in,
                              void* d_out, int out_size)
{
    const float* x    = (const float*)d_in[0];
    const int*   ei   = (const int*)d_in[1];
    const float* ea   = (const float*)d_in[2];
    const int*   si   = (const int*)d_in[3];
    const float* gm   = (const float*)d_in[4];
    const float* Wm   = (const float*)d_in[5];
    const float* bm   = (const float*)d_in[6];
    const float* Wn   = (const float*)d_in[7];
    const float* bn   = (const float*)d_in[8];
    const float* We   = (const float*)d_in[9];
    const float* be_  = (const float*)d_in[10];
    const float* Wih0 = (const float*)d_in[11];
    const float* Whh0 = (const float*)d_in[12];
    const float* bih0 = (const float*)d_in[13];
    const float* bhh0 = (const float*)d_in[14];
    const float* Wih1 = (const float*)d_in[15];
    const float* Whh1 = (const float*)d_in[16];
    const float* bih1 = (const float*)d_in[17];
    const float* bhh1 = (const float*)d_in[18];
    const float* Wd1  = (const float*)d_in[19];
    const float* bd1  = (const float*)d_in[20];
    const float* Wd2  = (const float*)d_in[21];
    const float* bd2  = (const float*)d_in[22];
    float* out = (float*)d_out;

    static cudaStream_t s1 = nullptr, s2 = nullptr;
    static cudaEvent_t evF = nullptr, evW = nullptr, evP = nullptr, evJ = nullptr;
    if (!s1) {
        cudaStreamCreateWithFlags(&s1, cudaStreamNonBlocking);
        cudaStreamCreateWithFlags(&s2, cudaStreamNonBlocking);
        cudaEventCreateWithFlags(&evF, cudaEventDisableTiming);
        cudaEventCreateWithFlags(&evW, cudaEventDisableTiming);
        cudaEventCreateWithFlags(&evP, cudaEventDisableTiming);
        cudaEventCreateWithFlags(&evJ, cudaEventDisableTiming);
        cudaFuncSetAttribute(sample_kernel,
                             cudaFuncAttributeMaxDynamicSharedMemorySize, SMEM_BYTES);
    }

    cudaEventRecord(evF, 0);
    cudaStreamWaitEvent(s1, evF, 0);
    cudaStreamWaitEvent(s2, evF, 0);

    // stream s2: weight prep, then P for all nodes (off the critical chain)
    prep_kernel<<<1124, 256, 0, s2>>>(Wih0, Whh0, Wih1, Whh1, We, Wd1,
                                      bih0, bhh0, bih1, bhh1);
    cudaEventRecord(evW, s2);
    preall_kernel<<<2 * NN / 256, 256, 0, s2>>>(x, Wm, bm);
    cudaEventRecord(evP, s2);

    // stream s1: half-1 chain
    flag_zero_kernel<<<NS2 / 8, 256, 0, s1>>>(si, 1);
    compact_edges_kernel<<<NE2 / 256, 256, 0, s1>>>(ei, 1);
    compact_nodes_kernel<<<NN2 / 256, 256, 0, s1>>>(1);
    cudaStreamWaitEvent(s1, evP, 0);
    edge_kernel<<<512, 256, 0, s1>>>(ea, Wm, 1);
    node_kernel<<<NS2 / 256, 256, 0, s1>>>(x, Wn, bn, 1);
    cudaStreamWaitEvent(s1, evW, 0);
    sample_kernel<<<NS2 / 64, 512, SMEM_BYTES, s1>>>(
        si, gm, be_, bd1, Wd2, bd2, out, 1);
    cudaEventRecord(evJ, s1);

    // default stream: half-0 chain
    flag_zero_kernel<<<NS2 / 8, 256>>>(si, 0);
    compact_edges_kernel<<<NE2 / 256, 256>>>(ei, 0);
    compact_nodes_kernel<<<NN2 / 256, 256>>>(0);
    cudaStreamWaitEvent(0, evP, 0);
    edge_kernel<<<512, 256>>>(ea, Wm, 0);
    node_kernel<<<NS2 / 256, 256>>>(x, Wn, bn, 0);
    cudaStreamWaitEvent(0, evW, 0);
    sample_kernel<<<NS2 / 64, 512, SMEM_BYTES>>>(
        si, gm, be_, bd1, Wd2, bd2, out, 0);

    cudaStreamWaitEvent(0, evJ, 0);
}

// round 16
// speedup vs baseline: 1.1033x; 1.1033x over previous
#include <cuda_runtime.h>
#include <cuda_fp16.h>
#include <math.h>
#include <stdint.h>

#define NN (64*4096)
#define NE (64*16384)
#define NS (64*1024)
#define NN2 (NN/2)
#define NE2 (NE/2)
#define NS2 (NS/2)
#define IN_F 26

typedef unsigned long long ull;

__device__ __align__(16) float g_agg[(size_t)NN * 64];
__device__ __align__(16) float g_conv[(size_t)NN * 64];
__device__ __align__(16) __half2 g_Ph[(size_t)NN * 64];   // [node][Psrc 32 | Pdst 32] half2
__device__ unsigned g_flagbits[NN / 32];                  // idempotent across replays
__device__ unsigned g_needsrc[NN / 32];                   // idempotent across replays
__device__ unsigned g_needdst[NN / 32];                   // idempotent across replays
__device__ int4  g_sde[NE];
__device__ int   g_nlist[NN];
__device__ int   g_plist[2 * NN];
__device__ int   g_cnt[8];
__device__ __align__(16) __half g_Wlh[512 * 512];
__device__ __align__(16) __half g_Weh[64 * 128];
__device__ __align__(16) __half g_Wd1h[256 * 64];
__device__ __align__(16) float  g_bc[2 * 512];

__device__ __forceinline__ ull pk(float lo, float hi) {
    ull r; asm("mov.b64 %0, {%1, %2};" : "=l"(r) : "f"(lo), "f"(hi)); return r;
}
__device__ __forceinline__ ull pk2(float v) { return pk(v, v); }
__device__ __forceinline__ float2 upk(ull v) {
    float2 r; asm("mov.b64 {%0, %1}, %2;" : "=f"(r.x), "=f"(r.y) : "l"(v)); return r;
}
__device__ __forceinline__ ull fma2(ull a, ull b, ull c) {
    ull d; asm("fma.rn.f32x2 %0, %1, %2, %3;" : "=l"(d) : "l"(a), "l"(b), "l"(c)); return d;
}
__device__ __forceinline__ float fsig(float x)  { return __fdividef(1.f, 1.f + __expf(-x)); }
__device__ __forceinline__ float ftanh(float x) { return 1.f - __fdividef(2.f, 1.f + __expf(2.f * x)); }

__device__ __forceinline__ float tf32v(float f) {
    uint32_t r; asm("cvt.rna.tf32.f32 %0, %1;" : "=r"(r) : "f"(f));
    return __uint_as_float(r);
}
__device__ __forceinline__ void mma8(float* d, const uint32_t* a, uint32_t b0, uint32_t b1) {
    asm volatile(
        "mma.sync.aligned.m16n8k8.row.col.f32.tf32.tf32.f32 "
        "{%0,%1,%2,%3}, {%4,%5,%6,%7}, {%8,%9}, {%0,%1,%2,%3};"
        : "+f"(d[0]), "+f"(d[1]), "+f"(d[2]), "+f"(d[3])
        : "r"(a[0]), "r"(a[1]), "r"(a[2]), "r"(a[3]), "r"(b0), "r"(b1));
}
__device__ __forceinline__ uint32_t ldb(const float* p) { return __float_as_uint(*p); }
__device__ __forceinline__ uint32_t ldh(const __half* p) {
    return __float_as_uint(__half2float(*p));
}
__device__ __forceinline__ uint32_t h2u(__half2 h) {
    uint32_t u; *(__half2*)&u = h; return u;
}
__device__ __forceinline__ void cp16(uint32_t dst, const void* src) {
    asm volatile("cp.async.cg.shared.global [%0], [%1], 16;" :: "r"(dst), "l"(src));
}
#define CP_COMMIT() asm volatile("cp.async.commit_group;")
#define CP_WAIT(n)  asm volatile("cp.async.wait_group " #n ";")
__device__ __forceinline__ void redv2(float* p, float a, float b) {
    asm volatile("red.global.add.v2.f32 [%0], {%1, %2};" :: "l"(p), "f"(a), "f"(b) : "memory");
}

// ---------------- prep: fp16 weight conversion ----------------
__global__ __launch_bounds__(256) void prep_kernel(
    const float* __restrict__ Wih0, const float* __restrict__ Whh0,
    const float* __restrict__ Wih1, const float* __restrict__ Whh1,
    const float* __restrict__ We,   const float* __restrict__ Wd1,
    const float* __restrict__ bih0, const float* __restrict__ bhh0,
    const float* __restrict__ bih1, const float* __restrict__ bhh1)
{
    int i = blockIdx.x * 256 + threadIdx.x;
    if (i < 262144) {
        int cell = i >> 17, r = (i >> 9) & 255, n = i & 511;
        const float* W = (r < 128) ? (cell ? Wih1 : Wih0) : (cell ? Whh1 : Whh0);
        g_Wlh[i] = __float2half(W[(r & 127) * 512 + n]);
    } else if (i < 270336) {
        int j = i - 262144; g_Weh[j] = __float2half(We[j]);
    } else if (i < 286720) {
        int j = i - 270336; g_Wd1h[j] = __float2half(Wd1[j]);
    } else if (i < 287744) {
        int j = i - 286720; int cell = j >> 9; int n = j & 511;
        g_bc[j] = cell ? (bih1[n] + bhh1[n]) : (bih0[n] + bhh0[n]);
    }
}

// ---------------- flag + zero agg rows + zero counters ----------------
__global__ __launch_bounds__(256) void flag_zero_kernel(const int* __restrict__ si, int h) {
    if (blockIdx.x == 0 && threadIdx.x < 4) g_cnt[h * 4 + threadIdx.x] = 0;
    int gw = blockIdx.x * 8 + (threadIdx.x >> 5);
    int l  = threadIdx.x & 31;
    int n  = si[h * NS2 + gw];
    if (l == 0) atomicOr(&g_flagbits[n >> 5], 1u << (n & 31));
    ((float2*)(g_agg + (size_t)n * 64))[l] = make_float2(0.f, 0.f);
}

__global__ __launch_bounds__(256) void compact_edges_kernel(const int* __restrict__ ei, int h) {
    int e = h * NE2 + blockIdx.x * 256 + threadIdx.x;
    int d = ei[NE + e];
    bool act = (g_flagbits[d >> 5] >> (d & 31)) & 1u;
    unsigned m = __ballot_sync(0xffffffffu, act);
    if (m) {
        int lane = threadIdx.x & 31;
        int leader = __ffs(m) - 1;
        int pos = 0;
        if (lane == leader) pos = atomicAdd(&g_cnt[h * 4], __popc(m));
        pos = __shfl_sync(0xffffffffu, pos, leader);
        pos += __popc(m & ((1u << lane) - 1));
        if (act) {
            int s = ei[e];
            g_sde[h * NE2 + pos] = make_int4(s, d, e, 0);
            atomicOr(&g_needsrc[s >> 5], 1u << (s & 31));
            atomicOr(&g_needdst[d >> 5], 1u << (d & 31));
        }
    }
}

__global__ __launch_bounds__(256) void compact_nodes_kernel(int h) {
    int n = h * NN2 + blockIdx.x * 256 + threadIdx.x;
    int lane = threadIdx.x & 31;
    {
        bool a = (g_flagbits[n >> 5] >> (n & 31)) & 1u;
        unsigned m = __ballot_sync(0xffffffffu, a);
        if (m) {
            int leader = __ffs(m) - 1;
            int pos = 0;
            if (lane == leader) pos = atomicAdd(&g_cnt[h * 4 + 1], __popc(m));
            pos = __shfl_sync(0xffffffffu, pos, leader);
            pos += __popc(m & ((1u << lane) - 1));
            if (a) g_nlist[h * NN2 + pos] = n;
        }
    }
    {
        bool a = (g_needsrc[n >> 5] >> (n & 31)) & 1u;
        unsigned m = __ballot_sync(0xffffffffu, a);
        if (m) {
            int leader = __ffs(m) - 1;
            int pos = 0;
            if (lane == leader) pos = atomicAdd(&g_cnt[h * 4 + 2], __popc(m));
            pos = __shfl_sync(0xffffffffu, pos, leader);
            pos += __popc(m & ((1u << lane) - 1));
            if (a) g_plist[h * NN + pos] = 2 * n;
        }
    }
    {
        bool a = (g_needdst[n >> 5] >> (n & 31)) & 1u;
        unsigned m = __ballot_sync(0xffffffffu, a);
        if (m) {
            int leader = __ffs(m) - 1;
            int pos = 0;
            if (lane == leader) pos = atomicAdd(&g_cnt[h * 4 + 2], __popc(m));
            pos = __shfl_sync(0xffffffffu, pos, leader);
            pos += __popc(m & ((1u << lane) - 1));
            if (a) g_plist[h * NN + pos] = 2 * n + 1;
        }
    }
}

// ---------------- pre: P halves stored fp16 (job list) ----------------
__global__ __launch_bounds__(256) void pre_kernel(
    const float* __restrict__ x, const float* __restrict__ Wm,
    const float* __restrict__ bm, int h)
{
    __shared__ float Ws[52 * 64];
    __shared__ float bs[64];
    for (int i = threadIdx.x; i < 52 * 64; i += 256) Ws[i] = Wm[i];
    if (threadIdx.x < 64) bs[threadIdx.x] = bm[threadIdx.x];
    __syncthreads();

    int i = blockIdx.x * 256 + threadIdx.x;
    if (i >= g_cnt[h * 4 + 2]) return;
    int job  = g_plist[h * NN + i];
    int n    = job >> 1;
    int half = job & 1;

    ull acc[32];
#pragma unroll
    for (int j = 0; j < 32; j++)
        acc[j] = half ? 0ull : pk(bs[2 * j], bs[2 * j + 1]);

    const float2* xr = (const float2*)(x + (size_t)n * IN_F);
    const int rbase = half * IN_F;
#pragma unroll
    for (int kk = 0; kk < 13; kk++) {
        float2 xv = xr[kk];
#pragma unroll
        for (int hh = 0; hh < 2; hh++) {
            ull v = pk2(hh ? xv.y : xv.x);
            const ulonglong2* wr = (const ulonglong2*)&Ws[(rbase + 2 * kk + hh) * 64];
#pragma unroll
            for (int j = 0; j < 16; j++) {
                ulonglong2 w = wr[j];
                acc[2 * j]     = fma2(v, w.x, acc[2 * j]);
                acc[2 * j + 1] = fma2(v, w.y, acc[2 * j + 1]);
            }
        }
    }
    uint4* dst = (uint4*)(g_Ph + (size_t)n * 64 + half * 32);
#pragma unroll
    for (int j = 0; j < 8; j++) {
        float2 a = upk(acc[4 * j]),     b = upk(acc[4 * j + 1]);
        float2 c = upk(acc[4 * j + 2]), d = upk(acc[4 * j + 3]);
        uint4 v;
        v.x = h2u(__floats2half2_rn(a.x, a.y));
        v.y = h2u(__floats2half2_rn(b.x, b.y));
        v.z = h2u(__floats2half2_rn(c.x, c.y));
        v.w = h2u(__floats2half2_rn(d.x, d.y));
        dst[j] = v;
    }
}

// ---------------- edges: fp16 P gathers ----------------
__global__ __launch_bounds__(256) void edge_kernel(const float* __restrict__ ea,
                                                   const float* __restrict__ Wm, int h)
{
    __shared__ float Ws[15 * 64];
    for (int i = threadIdx.x; i < 15 * 64; i += 256) Ws[i] = Wm[52 * 64 + i];
    __syncthreads();

    const int l  = threadIdx.x & 31;
    const int gw = blockIdx.x * 8 + (threadIdx.x >> 5);
    const int W  = gridDim.x * 8;
    const int ec = g_cnt[h * 4];

    for (int i = gw; i < ec; i += W) {
        int4 sde = g_sde[h * NE2 + i];
        float2 fs = __half22float2(g_Ph[(size_t)sde.x * 64 + l]);
        float2 fd = __half22float2(g_Ph[(size_t)sde.y * 64 + 32 + l]);
        ull acc = pk(fs.x + fd.x, fs.y + fd.y);
        const float* er = ea + (size_t)sde.z * 15;
#pragma unroll
        for (int k = 0; k < 15; k++) {
            ull w = *(const ull*)&Ws[k * 64 + 2 * l];
            acc = fma2(pk2(er[k]), w, acc);
        }
        float2 a = upk(acc);
        redv2(g_agg + (size_t)sde.y * 64 + 2 * l, fmaxf(a.x, 0.f), fmaxf(a.y, 0.f));
    }
}

__global__ __launch_bounds__(256) void node_kernel(
    const float* __restrict__ x, const float* __restrict__ Wn,
    const float* __restrict__ bn, int h)
{
    __shared__ float Ws[90 * 64];
    __shared__ float bs[64];
    for (int i = threadIdx.x; i < 90 * 64; i += 256) Ws[i] = Wn[i];
    if (threadIdx.x < 64) bs[threadIdx.x] = bn[threadIdx.x];
    __syncthreads();

    int i = blockIdx.x * 256 + threadIdx.x;
    if (i >= g_cnt[h * 4 + 1]) return;
    int n = g_nlist[h * NN2 + i];

    ull acc[32];
#pragma unroll
    for (int j = 0; j < 32; j++) acc[j] = pk(bs[2 * j], bs[2 * j + 1]);

    const float2* xr = (const float2*)(x + (size_t)n * IN_F);
#pragma unroll
    for (int kk = 0; kk < 13; kk++) {
        float2 xv = xr[kk];
#pragma unroll
        for (int hh = 0; hh < 2; hh++) {
            ull v = pk2(hh ? xv.y : xv.x);
            const ulonglong2* wr = (const ulonglong2*)&Ws[(2 * kk + hh) * 64];
#pragma unroll
            for (int j = 0; j < 16; j++) {
                ulonglong2 w = wr[j];
                acc[2 * j]     = fma2(v, w.x, acc[2 * j]);
                acc[2 * j + 1] = fma2(v, w.y, acc[2 * j + 1]);
            }
        }
    }
    const float4* ar = (const float4*)(g_agg + (size_t)n * 64);
#pragma unroll
    for (int kk = 0; kk < 16; kk++) {
        float4 av = ar[kk];
#pragma unroll
        for (int hh = 0; hh < 4; hh++) {
            float vf = hh == 0 ? av.x : hh == 1 ? av.y : hh == 2 ? av.z : av.w;
            ull v = pk2(vf);
            const ulonglong2* wr = (const ulonglong2*)&Ws[(IN_F + 4 * kk + hh) * 64];
#pragma unroll
            for (int j = 0; j < 16; j++) {
                ulonglong2 w = wr[j];
                acc[2 * j]     = fma2(v, w.x, acc[2 * j]);
                acc[2 * j + 1] = fma2(v, w.y, acc[2 * j + 1]);
            }
        }
    }
    float4* dst = (float4*)(g_conv + (size_t)n * 64);
#pragma unroll
    for (int j = 0; j < 16; j++) {
        float2 a = upk(acc[2 * j]), b = upk(acc[2 * j + 1]);
        dst[j] = make_float4(fmaxf(a.x, 0.f), fmaxf(a.y, 0.f),
                             fmaxf(b.x, 0.f), fmaxf(b.y, 0.f));
    }
}

// ---------------- fused sampled pipeline (validated R14 structure, unchanged) ----------------
#define O_NCT 0
#define O_A2  4352
#define O_XT  5632
#define O_HT  14080
#define O_WFL 22528
#define WBUF_H 8320
#define SMEM_BYTES (O_WFL * 4 + 3 * WBUF_H * 2)   // 140032

__global__ __launch_bounds__(512, 1) void sample_kernel(
    const int* __restrict__ sidx_g, const float* __restrict__ gm,
    const float* __restrict__ be, const float* __restrict__ bd1,
    const float* __restrict__ Wd2, const float* __restrict__ bd2,
    float* __restrict__ out, int h)
{
    extern __shared__ float sm[];
    float* nct = sm + O_NCT;
    float* A2  = sm + O_A2;
    float* Xt  = sm + O_XT;
    float* Ht  = sm + O_HT;
    __half* Wsh = (__half*)(sm + O_WFL);
    __shared__ float gmrow[10];
    __shared__ int   sidx[64];

    const int t    = threadIdx.x;
    const int base = h * NS2 + blockIdx.x * 64;
    const uint32_t wsh_u = (uint32_t)__cvta_generic_to_shared(Wsh);

    if (t < 64) sidx[t] = sidx_g[base + t];
    if (t < 10) gmrow[t] = gm[(base >> 10) * 10 + t];

    auto prefetch = [&](int c2) {
        uint32_t db = wsh_u + (uint32_t)((c2 % 3) * WBUF_H) * 2;
        if (c2 < 4) {
            if (t < 256) {
                int idx = t * 8; int kk = idx >> 7, n = idx & 127;
                cp16(db + (uint32_t)(kk * 520 + n) * 2, g_Weh + c2 * 2048 + idx);
            }
        } else if (c2 < 36) {
#pragma unroll
            for (int ii = 0; ii < 2; ii++) {
                int idx = (ii * 512 + t) * 8; int kk = idx >> 9, n = idx & 511;
                cp16(db + (uint32_t)(kk * 520 + n) * 2,
                     g_Wlh + (size_t)(c2 - 4) * 8192 + idx);
            }
        } else if (c2 < 52) {
            if (t < 128) {
                int idx = t * 8; int kk = idx >> 6, n = idx & 63;
                cp16(db + (uint32_t)(kk * 520 + n) * 2,
                     g_Wd1h + (c2 - 36) * 1024 + idx);
            }
        }
        CP_COMMIT();
    };
    prefetch(0);
    prefetch(1);

    __syncthreads();

    float* out_nc = out;
    float* out_h1 = out + (size_t)NS * 64;
    float* out_c1 = out_h1 + (size_t)NS * 128;
    float* out_h2 = out_c1 + (size_t)NS * 128;
    float* out_c2 = out_h2 + (size_t)NS * 128;
    float* out_y  = out_c2 + (size_t)NS * 128;

    for (int idx = t; idx < 64 * 64; idx += 512) {
        int r = idx >> 6, c = idx & 63;
        float v = g_conv[(size_t)sidx[r] * 64 + c];
        nct[r * 68 + c] = tf32v(v);
        out_nc[(size_t)(base + r) * 64 + c] = v;
    }
    for (int idx = t; idx < 64 * 20; idx += 512) {
        int r = idx / 20, kk = idx - r * 20;
        A2[idx] = (kk < 10) ? tf32v(g_conv[(size_t)sidx[r] * 64 + 54 + kk]) : 0.f;
    }
    __syncthreads();

    const int w    = t >> 5;
    const int lane = t & 31;
    const int g8   = lane >> 2;
    const int cc   = lane & 3;
    const int j0   = w * 8;
    const int col0 = j0 + 2 * cc, col1 = col0 + 1;

    float acc[64];
#pragma unroll
    for (int i = 0; i < 64; i++) acc[i] = 0.f;

    // encoder chunks 0..3
#pragma unroll 1
    for (int c = 0; c < 4; c++) {
        CP_WAIT(1);
        __syncthreads();
        prefetch(c + 2);
        const __half* wb = Wsh + (c % 3) * WBUF_H;
#pragma unroll
        for (int ks = 0; ks < 2; ks++) {
            int k0 = c * 16 + ks * 8;
            uint32_t b0 = ldh(&wb[(ks * 8 + cc) * 520 + j0 + g8]);
            uint32_t b1 = ldh(&wb[(ks * 8 + cc + 4) * 520 + j0 + g8]);
#pragma unroll
            for (int mt = 0; mt < 4; mt++) {
                int r0 = mt * 16 + g8;
                uint32_t a[4];
                a[0] = ldb(&nct[r0 * 68 + k0 + cc]);
                a[1] = ldb(&nct[(r0 + 8) * 68 + k0 + cc]);
                a[2] = ldb(&nct[r0 * 68 + k0 + cc + 4]);
                a[3] = ldb(&nct[(r0 + 8) * 68 + k0 + cc + 4]);
                mma8(acc + mt * 4, a, b0, b1);
            }
        }
    }

    // gm-correction mma + encoder epilogue (We rows 54..63 = buffer0 rows 6..15)
    {
        const __half* wb = Wsh;
#pragma unroll
        for (int ks = 0; ks < 2; ks++) {
            int k0 = ks * 8;
            uint32_t b0 = ldh(&wb[(6 + k0 + cc) * 520 + j0 + g8]);
            uint32_t b1 = ldh(&wb[(6 + k0 + cc + 4) * 520 + j0 + g8]);
#pragma unroll
            for (int mt = 0; mt < 4; mt++) {
                int r0 = mt * 16 + g8;
                uint32_t a[4];
                a[0] = ldb(&A2[r0 * 20 + k0 + cc]);
                a[1] = ldb(&A2[(r0 + 8) * 20 + k0 + cc]);
                a[2] = ldb(&A2[r0 * 20 + k0 + cc + 4]);
                a[3] = ldb(&A2[(r0 + 8) * 20 + k0 + cc + 4]);
                mma8(acc + 16 + mt * 4, a, b0, b1);
            }
        }
        float be0 = be[col0], be1 = be[col1];
        float gs0 = 0.f, gs1 = 0.f;
#pragma unroll
        for (int k = 0; k < 10; k++) {
            gs0 = fmaf(gmrow[k], __half2float(wb[(6 + k) * 520 + col0]), gs0);
            gs1 = fmaf(gmrow[k], __half2float(wb[(6 + k) * 520 + col1]), gs1);
        }
#pragma unroll
        for (int mt = 0; mt < 4; mt++) {
#pragma unroll
            for (int pp = 0; pp < 2; pp++) {
                int row = mt * 16 + g8 + pp * 8;
                float hp0 = acc[mt * 4 + pp * 2],      hp1 = acc[mt * 4 + pp * 2 + 1];
                float cr0 = acc[16 + mt * 4 + pp * 2], cr1 = acc[16 + mt * 4 + pp * 2 + 1];
                *(float2*)(Xt + row * 132 + col0) =
                    make_float2(tf32v(fmaxf(hp0 - cr0 + gs0 + be0, 0.f)),
                                tf32v(fmaxf(hp1 - cr1 + gs1 + be1, 0.f)));
                *(float2*)(Ht + row * 132 + col0) =
                    make_float2(tf32v(fmaxf(hp0 + be0, 0.f)),
                                tf32v(fmaxf(hp1 + be1, 0.f)));
            }
        }
#pragma unroll
        for (int i = 0; i < 64; i++) acc[i] = 0.f;
    }
    __syncthreads();

    // LSTM cells: chunks 4..35
#pragma unroll 1
    for (int cell = 0; cell < 2; cell++) {
        const int cbase = 4 + cell * 16;
#pragma unroll 1
        for (int cl = 0; cl < 16; cl++) {
            const int c = cbase + cl;
            CP_WAIT(1);
            __syncthreads();
            prefetch(c + 2);
            const int kl = cl * 16;
            const __half* wb = Wsh + (c % 3) * WBUF_H;
#pragma unroll
            for (int ks = 0; ks < 2; ks++) {
                int kg = kl + ks * 8;
                const float* At_ = (kg < 128) ? (Xt + kg) : (Ht + (kg - 128));
                uint32_t afr[4][4];
#pragma unroll
                for (int mt = 0; mt < 4; mt++) {
                    int r0 = mt * 16 + g8;
                    afr[mt][0] = ldb(&At_[r0 * 132 + cc]);
                    afr[mt][1] = ldb(&At_[(r0 + 8) * 132 + cc]);
                    afr[mt][2] = ldb(&At_[r0 * 132 + cc + 4]);
                    afr[mt][3] = ldb(&At_[(r0 + 8) * 132 + cc + 4]);
                }
#pragma unroll
                for (int q = 0; q < 4; q++) {
                    int ncol = q * 128 + j0 + g8;
                    uint32_t b0 = ldh(&wb[(ks * 8 + cc) * 520 + ncol]);
                    uint32_t b1 = ldh(&wb[(ks * 8 + cc + 4) * 520 + ncol]);
#pragma unroll
                    for (int mt = 0; mt < 4; mt++)
                        mma8(acc + mt * 16 + q * 4, afr[mt], b0, b1);
                }
            }
        }

        __syncthreads();
        {
            const float* bc = g_bc + cell * 512;
            float* oH = cell ? out_h2 : out_h1;
            float* oC = cell ? out_c2 : out_c1;
#pragma unroll
            for (int mt = 0; mt < 4; mt++) {
#pragma unroll
                for (int pp = 0; pp < 2; pp++) {
                    int row = mt * 16 + g8 + pp * 8;
                    int ib  = mt * 16 + pp * 2;
                    float vi0 = acc[ib + 0]  + bc[col0],       vi1 = acc[ib + 1]  + bc[col1];
                    float vf0 = acc[ib + 4]  + bc[128 + col0], vf1 = acc[ib + 5]  + bc[128 + col1];
                    float vg0 = acc[ib + 8]  + bc[256 + col0], vg1 = acc[ib + 9]  + bc[256 + col1];
                    float vo0 = acc[ib + 12] + bc[384 + col0], vo1 = acc[ib + 13] + bc[384 + col1];
                    float cp0 = Ht[row * 132 + col0], cp1 = Ht[row * 132 + col1];
                    float cv0 = fsig(vf0) * cp0 + fsig(vi0) * ftanh(vg0);
                    float cv1 = fsig(vf1) * cp1 + fsig(vi1) * ftanh(vg1);
                    float hv0 = fsig(vo0) * ftanh(cv0);
                    float hv1 = fsig(vo1) * ftanh(cv1);
                    size_t gi = (size_t)(base + row) * 128 + col0;
                    *(float2*)(oH + gi) = make_float2(hv0, hv1);
                    *(float2*)(oC + gi) = make_float2(cv0, cv1);
                    if (cell == 0) {
                        float nx0 = (col0 >= 118) ? gmrow[col0 - 118] : hv0;
                        float nx1 = (col1 >= 118) ? gmrow[col1 - 118] : hv1;
                        *(float2*)(Xt + row * 132 + col0) = make_float2(tf32v(nx0), tf32v(nx1));
                    } else {
                        *(float2*)(Xt + row * 132 + col0) = make_float2(tf32v(hv0), tf32v(hv1));
                        *(float2*)(Ht + row * 132 + col0) = make_float2(tf32v(cv0), tf32v(cv1));
                    }
                }
            }
#pragma unroll
            for (int i = 0; i < 64; i++) acc[i] = 0.f;
        }
        __syncthreads();
    }

    // decoder: chunks 36..51
    {
        const int n0  = (w & 7) * 8;
        const int mt0 = (w >> 3) * 2;
#pragma unroll 1
        for (int dl = 0; dl < 16; dl++) {
            const int c = 36 + dl;
            CP_WAIT(1);
            __syncthreads();
            prefetch(c + 2);
            const __half* wb = Wsh + (c % 3) * WBUF_H;
#pragma unroll
            for (int ks = 0; ks < 2; ks++) {
                int kg = dl * 16 + ks * 8;
                const float* At_ = (kg < 128) ? (Xt + kg) : (Ht + (kg - 128));
                uint32_t b0 = ldh(&wb[(ks * 8 + cc) * 520 + n0 + g8]);
                uint32_t b1 = ldh(&wb[(ks * 8 + cc + 4) * 520 + n0 + g8]);
#pragma unroll
                for (int m = 0; m < 2; m++) {
                    int r0 = (mt0 + m) * 16 + g8;
                    uint32_t a[4];
                    a[0] = ldb(&At_[r0 * 132 + cc]);
                    a[1] = ldb(&At_[(r0 + 8) * 132 + cc]);
                    a[2] = ldb(&At_[r0 * 132 + cc + 4]);
                    a[3] = ldb(&At_[(r0 + 8) * 132 + cc + 4]);
                    mma8(acc + m * 4, a, b0, b1);
                }
            }
        }
        __syncthreads();
        int c0 = n0 + 2 * cc, c1 = c0 + 1;
        float b0 = bd1[c0], b1 = bd1[c1];
#pragma unroll
        for (int m = 0; m < 2; m++) {
#pragma unroll
            for (int pp = 0; pp < 2; pp++) {
                int row = (mt0 + m) * 16 + g8 + pp * 8;
                float v0 = fmaxf(acc[m * 4 + pp * 2]     + b0, 0.f);
                float v1 = fmaxf(acc[m * 4 + pp * 2 + 1] + b1, 0.f);
                *(float2*)(nct + row * 68 + c0) = make_float2(v0, v1);
            }
        }
    }
    __syncthreads();

    if (t < 384) {
        int r = t / 6, c = t - r * 6;
        float accy = bd2[c];
#pragma unroll
        for (int k = 0; k < 64; k++) accy = fmaf(nct[r * 68 + k], Wd2[k * 6 + c], accy);
        out_y[(size_t)(base + r) * 6 + c] = accy;
    }
}

// ----------------------------------------------------------------
extern "C" void kernel_launch(void* const* d_in, const int* in_sizes, int n_in,
                              void* d_out, int out_size)
{
    const float* x    = (const float*)d_in[0];
    const int*   ei   = (const int*)d_in[1];
    const float* ea   = (const float*)d_in[2];
    const int*   si   = (const int*)d_in[3];
    const float* gm   = (const float*)d_in[4];
    const float* Wm   = (const float*)d_in[5];
    const float* bm   = (const float*)d_in[6];
    const float* Wn   = (const float*)d_in[7];
    const float* bn   = (const float*)d_in[8];
    const float* We   = (const float*)d_in[9];
    const float* be_  = (const float*)d_in[10];
    const float* Wih0 = (const float*)d_in[11];
    const float* Whh0 = (const float*)d_in[12];
    const float* bih0 = (const float*)d_in[13];
    const float* bhh0 = (const float*)d_in[14];
    const float* Wih1 = (const float*)d_in[15];
    const float* Whh1 = (const float*)d_in[16];
    const float* bih1 = (const float*)d_in[17];
    const float* bhh1 = (const float*)d_in[18];
    const float* Wd1  = (const float*)d_in[19];
    const float* bd1  = (const float*)d_in[20];
    const float* Wd2  = (const float*)d_in[21];
    const float* bd2  = (const float*)d_in[22];
    float* out = (float*)d_out;

    static cudaStream_t s1 = nullptr, s2 = nullptr;
    static cudaEvent_t evF = nullptr, evP = nullptr, evJ = nullptr;
    if (!s1) {
        cudaStreamCreateWithFlags(&s1, cudaStreamNonBlocking);
        cudaStreamCreateWithFlags(&s2, cudaStreamNonBlocking);
        cudaEventCreateWithFlags(&evF, cudaEventDisableTiming);
        cudaEventCreateWithFlags(&evP, cudaEventDisableTiming);
        cudaEventCreateWithFlags(&evJ, cudaEventDisableTiming);
        cudaFuncSetAttribute(sample_kernel,
                             cudaFuncAttributeMaxDynamicSharedMemorySize, SMEM_BYTES);
    }

    cudaEventRecord(evF, 0);
    cudaStreamWaitEvent(s1, evF, 0);
    cudaStreamWaitEvent(s2, evF, 0);

    // stream s2: weight prep only
    prep_kernel<<<1124, 256, 0, s2>>>(Wih0, Whh0, Wih1, Whh1, We, Wd1,
                                      bih0, bhh0, bih1, bhh1);
    cudaEventRecord(evP, s2);

    // stream s1: half-1 chain
    flag_zero_kernel<<<NS2 / 8, 256, 0, s1>>>(si, 1);
    compact_edges_kernel<<<NE2 / 256, 256, 0, s1>>>(ei, 1);
    compact_nodes_kernel<<<NN2 / 256, 256, 0, s1>>>(1);
    pre_kernel<<<NN / 256, 256, 0, s1>>>(x, Wm, bm, 1);
    edge_kernel<<<512, 256, 0, s1>>>(ea, Wm, 1);
    node_kernel<<<NS2 / 256, 256, 0, s1>>>(x, Wn, bn, 1);
    cudaStreamWaitEvent(s1, evP, 0);
    sample_kernel<<<NS2 / 64, 512, SMEM_BYTES, s1>>>(
        si, gm, be_, bd1, Wd2, bd2, out, 1);
    cudaEventRecord(evJ, s1);

    // default stream: half-0 chain
    flag_zero_kernel<<<NS2 / 8, 256>>>(si, 0);
    compact_edges_kernel<<<NE2 / 256, 256>>>(ei, 0);
    compact_nodes_kernel<<<NN2 / 256, 256>>>(0);
    pre_kernel<<<NN / 256, 256>>>(x, Wm, bm, 0);
    edge_kernel<<<512, 256>>>(ea, Wm, 0);
    node_kernel<<<NS2 / 256, 256>>>(x, Wn, bn, 0);
    cudaStreamWaitEvent(0, evP, 0);
    sample_kernel<<<NS2 / 64, 512, SMEM_BYTES>>>(
        si, gm, be_, bd1, Wd2, bd2, out, 0);

    cudaStreamWaitEvent(0, evJ, 0);
}